// round 10
// baseline (speedup 1.0000x reference)
#include <cuda_runtime.h>
#include <math.h>

#define BB 64
#define TT 256
#define IND 1024
#define HH 2048
#define MM 512
#define LL 2
#define CK 2560            // H + M
#define SPLITS 8
#define KC 16
#define SPAD 68

__device__ float g_xp[BB * TT * HH];
__device__ float g_comb[LL][BB * CK];         // per row: [ln-ed input (H) | h state (M)]
__device__ float g_lipart[SPLITS][BB * HH];
__device__ float g_upart[SPLITS][BB * MM];
__device__ float g_rpart[SPLITS][BB * MM];
__device__ float g_cpart[SPLITS][BB * MM];
__device__ float g_Wc[HH * MM];
__device__ float g_bc[HH];
__device__ float g_dbase[LL * MM];
__device__ unsigned int g_arrive;
__device__ volatile unsigned int g_release;

struct SP {
    const float *upd_W, *upd_b, *rst_W, *rst_b, *cell_W, *cell_b;
    const float *fb_W, *fb_b, *ln_w, *ln_b, *mn_w, *mn_b;
    float* out;
};
struct IP {
    const float *hidden, *tau, *lc_W, *lc_b, *sk_W, *sk_b;
};

__device__ __forceinline__ void gsync(unsigned int& target, int nblk) {
    __syncthreads();
    target += (unsigned int)nblk;
    if (threadIdx.x == 0) {
        __threadfence();
        unsigned int a = atomicAdd(&g_arrive, 1u) + 1u;
        if (a == target) {
            g_release = target;
        } else {
            while (g_release < target) { __nanosleep(64); }
            __threadfence();
        }
    }
    __syncthreads();
}

__device__ __forceinline__ float2 block_stats(float s1, float s2, float* red) {
    #pragma unroll
    for (int o = 16; o; o >>= 1) {
        s1 += __shfl_down_sync(0xffffffffu, s1, o);
        s2 += __shfl_down_sync(0xffffffffu, s2, o);
    }
    int w = threadIdx.x >> 5;
    if ((threadIdx.x & 31) == 0) { red[w] = s1; red[8 + w] = s2; }
    __syncthreads();
    if (threadIdx.x == 0) {
        float a = 0.f, b = 0.f;
        #pragma unroll
        for (int i = 0; i < 8; i++) { a += red[i]; b += red[8 + i]; }
        red[16] = a; red[17] = b;
    }
    __syncthreads();
    return make_float2(red[16], red[17]);
}

// C[row,col] = sum_{k=k0..k0+klen-1} A[row*lda+k]*W[col*ldw+k] (+bias[col]); 64x64 tile
__device__ __forceinline__ void gemm_tile(
    const float* __restrict__ A, int lda,
    const float* __restrict__ W, int ldw,
    float* __restrict__ C, int ldc,
    int k0, int klen, const float* __restrict__ bias,
    float* sA, float* sW)
{
    const int tid = threadIdx.x;
    const int tx = tid & 15, ty = tid >> 4;
    const int lk = tid & 15, lr = tid >> 4;

    float acc[4][4];
    #pragma unroll
    for (int i = 0; i < 4; i++)
        #pragma unroll
        for (int j = 0; j < 4; j++) acc[i][j] = 0.f;

    const float* Ag = A + (size_t)lr * lda + k0 + lk;
    const float* Wg = W + (size_t)lr * ldw + k0 + lk;
    float pa[4], pw[4];
    #pragma unroll
    for (int i = 0; i < 4; i++) {
        pa[i] = Ag[(size_t)(i * 16) * lda];
        pw[i] = Wg[(size_t)(i * 16) * ldw];
    }

    const int nch = klen / KC;
    for (int ch = 0; ch < nch; ch++) {
        __syncthreads();
        #pragma unroll
        for (int i = 0; i < 4; i++) {
            sA[lk * SPAD + lr + i * 16] = pa[i];
            sW[lk * SPAD + lr + i * 16] = pw[i];
        }
        __syncthreads();
        if (ch + 1 < nch) {
            const float* Ag2 = Ag + (ch + 1) * KC;
            const float* Wg2 = Wg + (ch + 1) * KC;
            #pragma unroll
            for (int i = 0; i < 4; i++) {
                pa[i] = Ag2[(size_t)(i * 16) * lda];
                pw[i] = Wg2[(size_t)(i * 16) * ldw];
            }
        }
        #pragma unroll
        for (int kk = 0; kk < KC; kk++) {
            float4 a = *(const float4*)(sA + kk * SPAD + (ty << 2));
            float4 w = *(const float4*)(sW + kk * SPAD + (tx << 2));
            acc[0][0] += a.x * w.x; acc[0][1] += a.x * w.y; acc[0][2] += a.x * w.z; acc[0][3] += a.x * w.w;
            acc[1][0] += a.y * w.x; acc[1][1] += a.y * w.y; acc[1][2] += a.y * w.z; acc[1][3] += a.y * w.w;
            acc[2][0] += a.z * w.x; acc[2][1] += a.z * w.y; acc[2][2] += a.z * w.z; acc[2][3] += a.z * w.w;
            acc[3][0] += a.w * w.x; acc[3][1] += a.w * w.y; acc[3][2] += a.w * w.z; acc[3][3] += a.w * w.w;
        }
    }

    #pragma unroll
    for (int i = 0; i < 4; i++) {
        float4 v = make_float4(acc[i][0], acc[i][1], acc[i][2], acc[i][3]);
        if (bias) {
            v.x += bias[tx * 4 + 0]; v.y += bias[tx * 4 + 1];
            v.z += bias[tx * 4 + 2]; v.w += bias[tx * 4 + 3];
        }
        *(float4*)(C + (size_t)(ty * 4 + i) * ldc + tx * 4) = v;
    }
}

__global__ void init_kernel(IP p) {
    int idx = blockIdx.x * blockDim.x + threadIdx.x;
    int stride = gridDim.x * blockDim.x;
    if (idx == 0) { g_arrive = 0; g_release = 0; }
    for (int i = idx; i < HH * MM; i += stride) g_Wc[i] = p.sk_W[i] + p.lc_W[i];
    for (int i = idx; i < HH; i += stride) g_bc[i] = p.sk_b[i] + p.lc_b[i];
    for (int i = idx; i < LL * MM; i += stride) {
        float ta = p.tau[i];
        float sp = (ta > 20.f) ? ta : log1pf(expf(ta));
        sp = fminf(fmaxf(sp, 0.1f), 10.f);
        g_dbase[i] = expf(-1.f / sp);
    }
    for (int i = idx; i < LL * BB * MM; i += stride) {
        int l = i / (BB * MM), rem = i % (BB * MM);
        g_comb[l][(rem / MM) * CK + HH + (rem % MM)] = p.hidden[i];
    }
}

__global__ void __launch_bounds__(256, 2) xp_kernel(
    const float* __restrict__ x, const float* __restrict__ W_in, const float* __restrict__ b_in)
{
    __shared__ __align__(16) float sm[2 * KC * SPAD];
    int n0 = blockIdx.x * 64;
    int r0 = blockIdx.y * 64;
    gemm_tile(x + (size_t)r0 * IND, IND,
              W_in + (size_t)n0 * IND, IND,
              g_xp + (size_t)r0 * HH + n0, HH,
              0, IND, b_in + n0, sm, sm + KC * SPAD);
}

__global__ void __launch_bounds__(256, 2) scan_kernel(SP p) {
    __shared__ __align__(16) float sm[2 * KC * SPAD];
    __shared__ float red[18];
    float* sA = sm;
    float* sW = sm + KC * SPAD;
    const int nblk = gridDim.x;
    unsigned int target = 0;

    for (int t = 0; t < TT; t++) {
        for (int l = 0; l < LL; l++) {
            if (l == 0) {
                if (t > 0) {
                    // feedback: h1_prev @ fb_W^T, K=512 split 8
                    for (int id = blockIdx.x; id < SPLITS * (HH / 64); id += nblk) {
                        int s = id >> 5, n0 = (id & 31) * 64;
                        gemm_tile(g_comb[1] + HH, CK,
                                  p.fb_W + (size_t)n0 * MM, MM,
                                  g_lipart[s] + n0, HH,
                                  s * (MM / SPLITS), MM / SPLITS, nullptr, sA, sW);
                    }
                    gsync(target, nblk);
                }
            } else {
                // h0_new @ (sk_W+lc_W)^T
                for (int id = blockIdx.x; id < SPLITS * (HH / 64); id += nblk) {
                    int s = id >> 5, n0 = (id & 31) * 64;
                    gemm_tile(g_comb[0] + HH, CK,
                              g_Wc + (size_t)n0 * MM, MM,
                              g_lipart[s] + n0, HH,
                              s * (MM / SPLITS), MM / SPLITS, nullptr, sA, sW);
                }
                gsync(target, nblk);
            }

            // layernorm over H (one block per batch row)
            for (int r = blockIdx.x; r < BB; r += nblk) {
                float v[8], s1 = 0.f, s2 = 0.f;
                #pragma unroll
                for (int j = 0; j < 8; j++) {
                    int h = threadIdx.x + j * 256;
                    float raw;
                    if (l == 0) {
                        raw = g_xp[(size_t)(r * TT + t) * HH + h];
                        if (t > 0) {
                            float d = p.fb_b[h];
                            #pragma unroll
                            for (int s = 0; s < SPLITS; s++) d += g_lipart[s][r * HH + h];
                            raw += 0.1f * d;
                        }
                    } else {
                        float d = g_bc[h];
                        #pragma unroll
                        for (int s = 0; s < SPLITS; s++) d += g_lipart[s][r * HH + h];
                        raw = d;
                    }
                    v[j] = raw; s1 += raw; s2 += raw * raw;
                }
                float2 S = block_stats(s1, s2, red);
                float mu = S.x * (1.f / HH);
                float var = S.y * (1.f / HH) - mu * mu;
                float inv = rsqrtf(var + 1e-5f);
                #pragma unroll
                for (int j = 0; j < 8; j++) {
                    int h = threadIdx.x + j * 256;
                    g_comb[l][r * CK + h] = (v[j] - mu) * inv * p.ln_w[l * HH + h] + p.ln_b[l * HH + h];
                }
                __syncthreads();
            }
            gsync(target, nblk);

            // gate GEMMs (u, r, cand), K split 8
            {
                const float* comb = g_comb[l];
                const int per = SPLITS * (MM / 64);
                for (int id = blockIdx.x; id < 3 * per; id += nblk) {
                    int g = id / per, rem = id % per;
                    int s = rem >> 3, n0 = (rem & 7) * 64;
                    if (g == 0)
                        gemm_tile(comb, CK, p.upd_W + (size_t)(l * MM + n0) * CK, CK,
                                  g_upart[s] + n0, MM, s * (CK / SPLITS), CK / SPLITS, nullptr, sA, sW);
                    else if (g == 1)
                        gemm_tile(comb, CK, p.rst_W + (size_t)(l * MM + n0) * CK, CK,
                                  g_rpart[s] + n0, MM, s * (CK / SPLITS), CK / SPLITS, nullptr, sA, sW);
                    else
                        gemm_tile(comb, CK, p.cell_W + (size_t)(l * MM + n0) * HH, HH,
                                  g_cpart[s] + n0, MM, s * (HH / SPLITS), HH / SPLITS, nullptr, sA, sW);
                }
            }
            gsync(target, nblk);

            // pointwise LTC update + mem-norm
            for (int r = blockIdx.x; r < BB; r += nblk) {
                float hv[2], s1 = 0.f, s2 = 0.f;
                #pragma unroll
                for (int j = 0; j < 2; j++) {
                    int m = threadIdx.x + j * 256;
                    float su = p.upd_b[l * MM + m];
                    float sr = p.rst_b[l * MM + m];
                    float sc = p.cell_b[l * MM + m];
                    #pragma unroll
                    for (int s = 0; s < SPLITS; s++) {
                        su += g_upart[s][r * MM + m];
                        sr += g_rpart[s][r * MM + m];
                        sc += g_cpart[s][r * MM + m];
                    }
                    float u  = 1.f / (1.f + expf(-su));
                    float rg = 1.f / (1.f + expf(-sr));
                    float c  = tanhf(sc);
                    float hold = g_comb[l][r * CK + HH + m];
                    float dec = g_dbase[l * MM + m] * u;
                    float hn = dec * (hold * rg) + (1.f - dec) * c;
                    hv[j] = hn; s1 += hn; s2 += hn * hn;
                }
                float2 S = block_stats(s1, s2, red);
                float mu = S.x * (1.f / MM);
                float var = S.y * (1.f / MM) - mu * mu;
                float inv = rsqrtf(var + 1e-5f);
                #pragma unroll
                for (int j = 0; j < 2; j++) {
                    int m = threadIdx.x + j * 256;
                    float hnorm = (hv[j] - mu) * inv * p.mn_w[l * MM + m] + p.mn_b[l * MM + m];
                    g_comb[l][r * CK + HH + m] = hnorm;
                    if (l == 1) p.out[(size_t)(r * TT + t) * MM + m] = hnorm;
                }
                __syncthreads();
            }
            gsync(target, nblk);
        }
    }

    for (int i = blockIdx.x * 256 + threadIdx.x; i < LL * BB * MM; i += nblk * 256) {
        int l = i / (BB * MM), rem = i % (BB * MM);
        p.out[(size_t)BB * TT * MM + i] = g_comb[l][(rem / MM) * CK + HH + (rem % MM)];
    }
}

extern "C" void kernel_launch(void* const* d_in, const int* in_sizes, int n_in,
                              void* d_out, int out_size) {
    (void)in_sizes; (void)n_in; (void)out_size;
    const float* x      = (const float*)d_in[0];
    const float* hidden = (const float*)d_in[1];
    const float* W_in   = (const float*)d_in[2];
    const float* b_in   = (const float*)d_in[3];

    IP ip;
    ip.hidden = hidden;
    ip.tau    = (const float*)d_in[10];
    ip.lc_W   = (const float*)d_in[11];
    ip.lc_b   = (const float*)d_in[12];
    ip.sk_W   = (const float*)d_in[13];
    ip.sk_b   = (const float*)d_in[14];

    SP sp;
    sp.cell_W = (const float*)d_in[4];
    sp.cell_b = (const float*)d_in[5];
    sp.upd_W  = (const float*)d_in[6];
    sp.upd_b  = (const float*)d_in[7];
    sp.rst_W  = (const float*)d_in[8];
    sp.rst_b  = (const float*)d_in[9];
    sp.fb_W   = (const float*)d_in[15];
    sp.fb_b   = (const float*)d_in[16];
    sp.ln_w   = (const float*)d_in[17];
    sp.ln_b   = (const float*)d_in[18];
    sp.mn_w   = (const float*)d_in[19];
    sp.mn_b   = (const float*)d_in[20];
    sp.out    = (float*)d_out;

    int dev = 0;
    cudaGetDevice(&dev);
    cudaDeviceProp prop;
    cudaGetDeviceProperties(&prop, dev);
    int occ = 0;
    cudaOccupancyMaxActiveBlocksPerMultiprocessor(&occ, scan_kernel, 256, 0);
    if (occ < 1) occ = 1;
    if (occ > 2) occ = 2;
    int nblk = prop.multiProcessorCount * occ;

    init_kernel<<<256, 256>>>(ip);
    dim3 gx(HH / 64, (BB * TT) / 64);
    xp_kernel<<<gx, 256>>>(x, W_in, b_in);
    scan_kernel<<<nblk, 256>>>(sp);
}

// round 11
// speedup vs baseline: 1.0339x; 1.0339x over previous
#include <cuda_runtime.h>
#include <math.h>

#define BB 64
#define TT 256
#define IND 1024
#define HH 2048
#define MM 512
#define LL 2
#define CK 2560            // H + M
#define SPLITS 8           // K-splits for fb/lc and xp
#define SU 13              // K-splits for upd/rst GEMMs (K=2560 -> 160 chunks)
#define SC 10              // K-splits for cand GEMM    (K=2048 -> 128 chunks)
#define NTG (16*SU + 8*SC) // 288 gate tiles per layer
#define KC 16
#define SPAD 68

__device__ float g_xpp[3][SPLITS][BB * HH];   // xp partials, 3-slot ring over t
__device__ float g_comb[LL][BB * CK];         // per row: [ln-ed input (H) | h state (M)]
__device__ float g_lipart[SPLITS][BB * HH];
__device__ float g_upart[SU][BB * MM];
__device__ float g_rpart[SU][BB * MM];
__device__ float g_cpart[SC][BB * MM];
__device__ float g_Wc[HH * MM];
__device__ float g_bc[HH];
__device__ float g_dbase[LL * MM];
__device__ unsigned int g_arrive;
__device__ volatile unsigned int g_release;

struct SP {
    const float *x, *W_in, *b_in;
    const float *upd_W, *upd_b, *rst_W, *rst_b, *cell_W, *cell_b;
    const float *fb_W, *fb_b, *ln_w, *ln_b, *mn_w, *mn_b;
    float* out;
};
struct IP {
    const float *hidden, *tau, *lc_W, *lc_b, *sk_W, *sk_b;
};

__device__ __forceinline__ void gsync(unsigned int& target, int nblk) {
    __syncthreads();
    target += (unsigned int)nblk;
    if (threadIdx.x == 0) {
        __threadfence();
        unsigned int a = atomicAdd(&g_arrive, 1u) + 1u;
        if (a == target) {
            g_release = target;
        } else {
            while (g_release < target) { }
            __threadfence();
        }
    }
    __syncthreads();
}

__device__ __forceinline__ float2 block_stats(float s1, float s2, float* red) {
    #pragma unroll
    for (int o = 16; o; o >>= 1) {
        s1 += __shfl_down_sync(0xffffffffu, s1, o);
        s2 += __shfl_down_sync(0xffffffffu, s2, o);
    }
    int w = threadIdx.x >> 5;
    if ((threadIdx.x & 31) == 0) { red[w] = s1; red[8 + w] = s2; }
    __syncthreads();
    if (threadIdx.x == 0) {
        float a = 0.f, b = 0.f;
        #pragma unroll
        for (int i = 0; i < 8; i++) { a += red[i]; b += red[8 + i]; }
        red[16] = a; red[17] = b;
    }
    __syncthreads();
    return make_float2(red[16], red[17]);
}

// C[row,col] = sum_{k=k0..k0+klen-1} A[row*lda+k]*W[col*ldw+k] (+bias[col]); 64x64 tile
__device__ __forceinline__ void gemm_tile(
    const float* __restrict__ A, size_t lda,
    const float* __restrict__ W, size_t ldw,
    float* __restrict__ C, int ldc,
    int k0, int klen, const float* __restrict__ bias,
    float* sA, float* sW)
{
    const int tid = threadIdx.x;
    const int tx = tid & 15, ty = tid >> 4;
    const int lk = tid & 15, lr = tid >> 4;

    float acc[4][4];
    #pragma unroll
    for (int i = 0; i < 4; i++)
        #pragma unroll
        for (int j = 0; j < 4; j++) acc[i][j] = 0.f;

    const float* Ag = A + (size_t)lr * lda + k0 + lk;
    const float* Wg = W + (size_t)lr * ldw + k0 + lk;
    float pa[4], pw[4];
    #pragma unroll
    for (int i = 0; i < 4; i++) {
        pa[i] = Ag[(size_t)(i * 16) * lda];
        pw[i] = Wg[(size_t)(i * 16) * ldw];
    }

    const int nch = klen / KC;
    for (int ch = 0; ch < nch; ch++) {
        __syncthreads();
        #pragma unroll
        for (int i = 0; i < 4; i++) {
            sA[lk * SPAD + lr + i * 16] = pa[i];
            sW[lk * SPAD + lr + i * 16] = pw[i];
        }
        __syncthreads();
        if (ch + 1 < nch) {
            const float* Ag2 = Ag + (ch + 1) * KC;
            const float* Wg2 = Wg + (ch + 1) * KC;
            #pragma unroll
            for (int i = 0; i < 4; i++) {
                pa[i] = Ag2[(size_t)(i * 16) * lda];
                pw[i] = Wg2[(size_t)(i * 16) * ldw];
            }
        }
        #pragma unroll
        for (int kk = 0; kk < KC; kk++) {
            float4 a = *(const float4*)(sA + kk * SPAD + (ty << 2));
            float4 w = *(const float4*)(sW + kk * SPAD + (tx << 2));
            acc[0][0] += a.x * w.x; acc[0][1] += a.x * w.y; acc[0][2] += a.x * w.z; acc[0][3] += a.x * w.w;
            acc[1][0] += a.y * w.x; acc[1][1] += a.y * w.y; acc[1][2] += a.y * w.z; acc[1][3] += a.y * w.w;
            acc[2][0] += a.z * w.x; acc[2][1] += a.z * w.y; acc[2][2] += a.z * w.z; acc[2][3] += a.z * w.w;
            acc[3][0] += a.w * w.x; acc[3][1] += a.w * w.y; acc[3][2] += a.w * w.z; acc[3][3] += a.w * w.w;
        }
    }

    #pragma unroll
    for (int i = 0; i < 4; i++) {
        float4 v = make_float4(acc[i][0], acc[i][1], acc[i][2], acc[i][3]);
        if (bias) {
            v.x += bias[tx * 4 + 0]; v.y += bias[tx * 4 + 1];
            v.z += bias[tx * 4 + 2]; v.w += bias[tx * 4 + 3];
        }
        *(float4*)(C + (size_t)(ty * 4 + i) * ldc + tx * 4) = v;
    }
}

__global__ void init_kernel(IP p) {
    int idx = blockIdx.x * blockDim.x + threadIdx.x;
    int stride = gridDim.x * blockDim.x;
    if (idx == 0) { g_arrive = 0; g_release = 0; }
    for (int i = idx; i < HH * MM; i += stride) g_Wc[i] = p.sk_W[i] + p.lc_W[i];
    for (int i = idx; i < HH; i += stride) g_bc[i] = p.sk_b[i] + p.lc_b[i];
    for (int i = idx; i < LL * MM; i += stride) {
        float ta = p.tau[i];
        float sp = (ta > 20.f) ? ta : log1pf(expf(ta));
        sp = fminf(fmaxf(sp, 0.1f), 10.f);
        g_dbase[i] = expf(-1.f / sp);
    }
    for (int i = idx; i < LL * BB * MM; i += stride) {
        int l = i / (BB * MM), rem = i % (BB * MM);
        g_comb[l][(rem / MM) * CK + HH + (rem % MM)] = p.hidden[i];
    }
}

// Produce xp partial tiles for timestep t+2 (blocks 64..127, one tile each per phase).
// xp[t][b][h] = sum_i x[b][t][i] * W_in[h][i]; split K=1024 into 8 x 128.
__device__ __forceinline__ void xp_produce(const SP& p, int t, int phase,
                                           float* sA, float* sW) {
    int tp = t + 2;
    if (tp >= TT) return;
    int bi = (int)blockIdx.x - BB;
    if (bi < 0 || bi >= 64) return;
    int id = phase * 64 + bi;          // 0..255
    int s = id >> 5, c = id & 31;
    gemm_tile(p.x + (size_t)tp * IND, (size_t)TT * IND,
              p.W_in + (size_t)(c * 64) * IND, IND,
              g_xpp[tp % 3][s] + c * 64, HH,
              s * 128, 128, nullptr, sA, sW);
}

__global__ void __launch_bounds__(256, 2) scan_kernel(SP p) {
    __shared__ __align__(16) float sm[2 * KC * SPAD];
    __shared__ float red[18];
    float* sA = sm;
    float* sW = sm + KC * SPAD;
    const int nblk = gridDim.x;
    unsigned int target = 0;

    // prologue: xp for t=0,1 (512 tiles)
    for (int id = blockIdx.x; id < 2 * 256; id += nblk) {
        int tt = id >> 8;
        int rem = id & 255;
        int s = rem >> 5, c = rem & 31;
        gemm_tile(p.x + (size_t)tt * IND, (size_t)TT * IND,
                  p.W_in + (size_t)(c * 64) * IND, IND,
                  g_xpp[tt][s] + c * 64, HH,
                  s * 128, 128, nullptr, sA, sW);
    }
    gsync(target, nblk);

    for (int t = 0; t < TT; t++) {
        for (int l = 0; l < LL; l++) {
            // ---- pre-activation GEMM (K-split partials) ----
            if (l == 0) {
                if (t > 0) {
                    for (int id = blockIdx.x; id < SPLITS * (HH / 64); id += nblk) {
                        int s = id >> 5, n0 = (id & 31) * 64;
                        gemm_tile(g_comb[1] + HH, CK,
                                  p.fb_W + (size_t)n0 * MM, MM,
                                  g_lipart[s] + n0, HH,
                                  s * (MM / SPLITS), MM / SPLITS, nullptr, sA, sW);
                    }
                    gsync(target, nblk);
                }
            } else {
                for (int id = blockIdx.x; id < SPLITS * (HH / 64); id += nblk) {
                    int s = id >> 5, n0 = (id & 31) * 64;
                    gemm_tile(g_comb[0] + HH, CK,
                              g_Wc + (size_t)n0 * MM, MM,
                              g_lipart[s] + n0, HH,
                              s * (MM / SPLITS), MM / SPLITS, nullptr, sA, sW);
                }
                gsync(target, nblk);
            }

            // ---- layernorm over H (blocks 0..63) | xp production (blocks 64..127) ----
            if (blockIdx.x < BB) {
                int r = blockIdx.x;
                float v[8], s1 = 0.f, s2 = 0.f;
                #pragma unroll
                for (int j = 0; j < 8; j++) {
                    int h = threadIdx.x + j * 256;
                    float raw;
                    if (l == 0) {
                        raw = p.b_in[h];
                        #pragma unroll
                        for (int s = 0; s < SPLITS; s++) raw += g_xpp[t % 3][s][r * HH + h];
                        if (t > 0) {
                            float d = p.fb_b[h];
                            #pragma unroll
                            for (int s = 0; s < SPLITS; s++) d += g_lipart[s][r * HH + h];
                            raw += 0.1f * d;
                        }
                    } else {
                        float d = g_bc[h];
                        #pragma unroll
                        for (int s = 0; s < SPLITS; s++) d += g_lipart[s][r * HH + h];
                        raw = d;
                    }
                    v[j] = raw; s1 += raw; s2 += raw * raw;
                }
                float2 S = block_stats(s1, s2, red);
                float mu = S.x * (1.f / HH);
                float var = S.y * (1.f / HH) - mu * mu;
                float inv = rsqrtf(var + 1e-5f);
                #pragma unroll
                for (int j = 0; j < 8; j++) {
                    int h = threadIdx.x + j * 256;
                    g_comb[l][r * CK + h] = (v[j] - mu) * inv * p.ln_w[l * HH + h] + p.ln_b[l * HH + h];
                }
            } else {
                xp_produce(p, t, l == 0 ? 0 : 2, sA, sW);
            }
            gsync(target, nblk);

            // ---- gate GEMMs (u, r, cand), balanced K-splits ----
            {
                const float* comb = g_comb[l];
                for (int id = blockIdx.x; id < NTG; id += nblk) {
                    if (id < 8 * SU) {
                        int s = id >> 3, n0 = (id & 7) * 64;
                        int c0 = (160 * s) / SU, c1 = (160 * (s + 1)) / SU;
                        gemm_tile(comb, CK, p.upd_W + (size_t)(l * MM + n0) * CK, CK,
                                  g_upart[s] + n0, MM, c0 * 16, (c1 - c0) * 16, nullptr, sA, sW);
                    } else if (id < 16 * SU) {
                        int j = id - 8 * SU;
                        int s = j >> 3, n0 = (j & 7) * 64;
                        int c0 = (160 * s) / SU, c1 = (160 * (s + 1)) / SU;
                        gemm_tile(comb, CK, p.rst_W + (size_t)(l * MM + n0) * CK, CK,
                                  g_rpart[s] + n0, MM, c0 * 16, (c1 - c0) * 16, nullptr, sA, sW);
                    } else {
                        int j = id - 16 * SU;
                        int s = j >> 3, n0 = (j & 7) * 64;
                        int c0 = (128 * s) / SC, c1 = (128 * (s + 1)) / SC;
                        gemm_tile(comb, CK, p.cell_W + (size_t)(l * MM + n0) * HH, HH,
                                  g_cpart[s] + n0, MM, c0 * 16, (c1 - c0) * 16, nullptr, sA, sW);
                    }
                }
            }
            gsync(target, nblk);

            // ---- pointwise LTC update + mem-norm (blocks 0..63) | xp production ----
            if (blockIdx.x < BB) {
                int r = blockIdx.x;
                float hv[2], s1 = 0.f, s2 = 0.f;
                #pragma unroll
                for (int j = 0; j < 2; j++) {
                    int m = threadIdx.x + j * 256;
                    float su = p.upd_b[l * MM + m];
                    float sr = p.rst_b[l * MM + m];
                    float sc = p.cell_b[l * MM + m];
                    #pragma unroll
                    for (int s = 0; s < SU; s++) {
                        su += g_upart[s][r * MM + m];
                        sr += g_rpart[s][r * MM + m];
                    }
                    #pragma unroll
                    for (int s = 0; s < SC; s++) sc += g_cpart[s][r * MM + m];
                    float u  = 1.f / (1.f + expf(-su));
                    float rg = 1.f / (1.f + expf(-sr));
                    float c  = tanhf(sc);
                    float hold = g_comb[l][r * CK + HH + m];
                    float dec = g_dbase[l * MM + m] * u;
                    float hn = dec * (hold * rg) + (1.f - dec) * c;
                    hv[j] = hn; s1 += hn; s2 += hn * hn;
                }
                float2 S = block_stats(s1, s2, red);
                float mu = S.x * (1.f / MM);
                float var = S.y * (1.f / MM) - mu * mu;
                float inv = rsqrtf(var + 1e-5f);
                #pragma unroll
                for (int j = 0; j < 2; j++) {
                    int m = threadIdx.x + j * 256;
                    float hnorm = (hv[j] - mu) * inv * p.mn_w[l * MM + m] + p.mn_b[l * MM + m];
                    g_comb[l][r * CK + HH + m] = hnorm;
                    if (l == 1) p.out[(size_t)(r * TT + t) * MM + m] = hnorm;
                }
            } else {
                xp_produce(p, t, l == 0 ? 1 : 3, sA, sW);
            }
            gsync(target, nblk);
        }
    }

    for (int i = blockIdx.x * 256 + threadIdx.x; i < LL * BB * MM; i += nblk * 256) {
        int l = i / (BB * MM), rem = i % (BB * MM);
        p.out[(size_t)BB * TT * MM + i] = g_comb[l][(rem / MM) * CK + HH + (rem % MM)];
    }
}

extern "C" void kernel_launch(void* const* d_in, const int* in_sizes, int n_in,
                              void* d_out, int out_size) {
    (void)in_sizes; (void)n_in; (void)out_size;

    IP ip;
    ip.hidden = (const float*)d_in[1];
    ip.tau    = (const float*)d_in[10];
    ip.lc_W   = (const float*)d_in[11];
    ip.lc_b   = (const float*)d_in[12];
    ip.sk_W   = (const float*)d_in[13];
    ip.sk_b   = (const float*)d_in[14];

    SP sp;
    sp.x      = (const float*)d_in[0];
    sp.W_in   = (const float*)d_in[2];
    sp.b_in   = (const float*)d_in[3];
    sp.cell_W = (const float*)d_in[4];
    sp.cell_b = (const float*)d_in[5];
    sp.upd_W  = (const float*)d_in[6];
    sp.upd_b  = (const float*)d_in[7];
    sp.rst_W  = (const float*)d_in[8];
    sp.rst_b  = (const float*)d_in[9];
    sp.fb_W   = (const float*)d_in[15];
    sp.fb_b   = (const float*)d_in[16];
    sp.ln_w   = (const float*)d_in[17];
    sp.ln_b   = (const float*)d_in[18];
    sp.mn_w   = (const float*)d_in[19];
    sp.mn_b   = (const float*)d_in[20];
    sp.out    = (float*)d_out;

    int dev = 0;
    cudaGetDevice(&dev);
    cudaDeviceProp prop;
    cudaGetDeviceProperties(&prop, dev);
    int occ = 0;
    cudaOccupancyMaxActiveBlocksPerMultiprocessor(&occ, scan_kernel, 256, 0);
    if (occ < 1) occ = 1;
    if (occ > 2) occ = 2;
    int nblk = prop.multiProcessorCount * occ;

    init_kernel<<<256, 256>>>(ip);
    scan_kernel<<<nblk, 256>>>(sp);
}

// round 13
// speedup vs baseline: 1.0917x; 1.0559x over previous
#include <cuda_runtime.h>
#include <math.h>

#define BB 64
#define TT 256
#define IND 1024
#define HH 2048
#define MM 512
#define LL 2
#define CK 2560            // H + M
#define SPLITS 8           // K-splits for fb/lc and xp
#define SU 13              // K-splits for upd/rst GEMMs (K=2560 -> 160 chunks)
#define SC 10              // K-splits for cand GEMM    (K=2048 -> 128 chunks)
#define NTG (16*SU + 8*SC) // 288 gate tiles per layer
#define KC 16
#define SPAD 68

__device__ float g_xpp[3][SPLITS][BB * HH];   // xp partials, 3-slot ring over t
__device__ float g_comb[LL][BB * CK];         // per row: [ln-ed input (H) | h state (M)]
__device__ float g_lipart[SPLITS][BB * HH];
__device__ float g_upart[SU][BB * MM];
__device__ float g_rpart[SU][BB * MM];
__device__ float g_cpart[SC][BB * MM];
__device__ float g_Wc[HH * MM];
__device__ float g_bc[HH];
__device__ float g_dbase[LL * MM];
__device__ unsigned int g_arrive;
__device__ volatile unsigned int g_release;

struct SP {
    const float *x, *W_in, *b_in;
    const float *upd_W, *upd_b, *rst_W, *rst_b, *cell_W, *cell_b;
    const float *fb_W, *fb_b, *ln_w, *ln_b, *mn_w, *mn_b;
    float* out;
};
struct IP {
    const float *hidden, *tau, *lc_W, *lc_b, *sk_W, *sk_b;
};

__device__ __forceinline__ void gsync(unsigned int& target, int nblk) {
    __syncthreads();
    target += (unsigned int)nblk;
    if (threadIdx.x == 0) {
        __threadfence();
        unsigned int a = atomicAdd(&g_arrive, 1u) + 1u;
        if (a == target) {
            g_release = target;
        } else {
            while (g_release < target) { }
            __threadfence();
        }
    }
    __syncthreads();
}

__device__ __forceinline__ float2 block_stats(float s1, float s2, float* red) {
    #pragma unroll
    for (int o = 16; o; o >>= 1) {
        s1 += __shfl_down_sync(0xffffffffu, s1, o);
        s2 += __shfl_down_sync(0xffffffffu, s2, o);
    }
    int w = threadIdx.x >> 5;
    if ((threadIdx.x & 31) == 0) { red[w] = s1; red[8 + w] = s2; }
    __syncthreads();
    if (threadIdx.x == 0) {
        float a = 0.f, b = 0.f;
        #pragma unroll
        for (int i = 0; i < 8; i++) { a += red[i]; b += red[8 + i]; }
        red[16] = a; red[17] = b;
    }
    __syncthreads();
    return make_float2(red[16], red[17]);
}

// ---- packed f32x2 helpers (Blackwell: fma.rn.f32x2 doubles fp32 FMA rate) ----
__device__ __forceinline__ unsigned long long dup2(float x) {
    unsigned long long r;
    asm("mov.b64 %0, {%1, %1};" : "=l"(r) : "f"(x));
    return r;
}
__device__ __forceinline__ void fma2(unsigned long long& d,
                                     unsigned long long a, unsigned long long b) {
    asm("fma.rn.f32x2 %0, %1, %2, %0;" : "+l"(d) : "l"(a), "l"(b));
}
__device__ __forceinline__ float2 unpk2(unsigned long long v) {
    float2 r;
    asm("mov.b64 {%0, %1}, %2;" : "=f"(r.x), "=f"(r.y) : "l"(v));
    return r;
}

// C[row,col] = sum_{k=k0..k0+klen-1} A[row*lda+k]*W[col*ldw+k] (+bias[col]); 64x64 tile
__device__ __forceinline__ void gemm_tile(
    const float* __restrict__ A, size_t lda,
    const float* __restrict__ W, size_t ldw,
    float* __restrict__ C, int ldc,
    int k0, int klen, const float* __restrict__ bias,
    float* sA, float* sW)
{
    const int tid = threadIdx.x;
    const int tx = tid & 15, ty = tid >> 4;
    const int lk = tid & 15, lr = tid >> 4;

    // acc[i][0] = cols {4tx+0, 4tx+1}, acc[i][1] = cols {4tx+2, 4tx+3} for row 4ty+i
    unsigned long long acc[4][2];
    #pragma unroll
    for (int i = 0; i < 4; i++) { acc[i][0] = 0ull; acc[i][1] = 0ull; }

    const float* Ag = A + (size_t)lr * lda + k0 + lk;
    const float* Wg = W + (size_t)lr * ldw + k0 + lk;
    float pa[4], pw[4];
    #pragma unroll
    for (int i = 0; i < 4; i++) {
        pa[i] = Ag[(size_t)(i * 16) * lda];
        pw[i] = Wg[(size_t)(i * 16) * ldw];
    }

    const int nch = klen / KC;
    for (int ch = 0; ch < nch; ch++) {
        __syncthreads();
        #pragma unroll
        for (int i = 0; i < 4; i++) {
            sA[lk * SPAD + lr + i * 16] = pa[i];
            sW[lk * SPAD + lr + i * 16] = pw[i];
        }
        __syncthreads();
        if (ch + 1 < nch) {
            const float* Ag2 = Ag + (ch + 1) * KC;
            const float* Wg2 = Wg + (ch + 1) * KC;
            #pragma unroll
            for (int i = 0; i < 4; i++) {
                pa[i] = Ag2[(size_t)(i * 16) * lda];
                pw[i] = Wg2[(size_t)(i * 16) * ldw];
            }
        }
        #pragma unroll
        for (int kk = 0; kk < KC; kk++) {
            float4 a = *(const float4*)(sA + kk * SPAD + (ty << 2));
            ulonglong2 w = *(const ulonglong2*)(sW + kk * SPAD + (tx << 2));
            unsigned long long a0 = dup2(a.x), a1 = dup2(a.y);
            unsigned long long a2 = dup2(a.z), a3 = dup2(a.w);
            fma2(acc[0][0], a0, w.x); fma2(acc[0][1], a0, w.y);
            fma2(acc[1][0], a1, w.x); fma2(acc[1][1], a1, w.y);
            fma2(acc[2][0], a2, w.x); fma2(acc[2][1], a2, w.y);
            fma2(acc[3][0], a3, w.x); fma2(acc[3][1], a3, w.y);
        }
    }

    #pragma unroll
    for (int i = 0; i < 4; i++) {
        float2 c01 = unpk2(acc[i][0]);
        float2 c23 = unpk2(acc[i][1]);
        float4 v = make_float4(c01.x, c01.y, c23.x, c23.y);
        if (bias) {
            v.x += bias[tx * 4 + 0]; v.y += bias[tx * 4 + 1];
            v.z += bias[tx * 4 + 2]; v.w += bias[tx * 4 + 3];
        }
        *(float4*)(C + (size_t)(ty * 4 + i) * ldc + tx * 4) = v;
    }
}

__global__ void init_kernel(IP p) {
    int idx = blockIdx.x * blockDim.x + threadIdx.x;
    int stride = gridDim.x * blockDim.x;
    if (idx == 0) { g_arrive = 0; g_release = 0; }
    for (int i = idx; i < HH * MM; i += stride) g_Wc[i] = p.sk_W[i] + p.lc_W[i];
    for (int i = idx; i < HH; i += stride) g_bc[i] = p.sk_b[i] + p.lc_b[i];
    for (int i = idx; i < LL * MM; i += stride) {
        float ta = p.tau[i];
        float sp = (ta > 20.f) ? ta : log1pf(expf(ta));
        sp = fminf(fmaxf(sp, 0.1f), 10.f);
        g_dbase[i] = expf(-1.f / sp);
    }
    for (int i = idx; i < LL * BB * MM; i += stride) {
        int l = i / (BB * MM), rem = i % (BB * MM);
        g_comb[l][(rem / MM) * CK + HH + (rem % MM)] = p.hidden[i];
    }
}

// Produce xp partial tiles for timestep t+2 (blocks 64..127, one tile each per phase).
__device__ __forceinline__ void xp_produce(const SP& p, int t, int phase,
                                           float* sA, float* sW) {
    int tp = t + 2;
    if (tp >= TT) return;
    int bi = (int)blockIdx.x - BB;
    if (bi < 0 || bi >= 64) return;
    int id = phase * 64 + bi;          // 0..255
    int s = id >> 5, c = id & 31;
    gemm_tile(p.x + (size_t)tp * IND, (size_t)TT * IND,
              p.W_in + (size_t)(c * 64) * IND, IND,
              g_xpp[tp % 3][s] + c * 64, HH,
              s * 128, 128, nullptr, sA, sW);
}

__global__ void __launch_bounds__(256, 2) scan_kernel(SP p) {
    __shared__ __align__(16) float sm[2 * KC * SPAD];
    __shared__ float red[18];
    float* sA = sm;
    float* sW = sm + KC * SPAD;
    const int nblk = gridDim.x;
    unsigned int target = 0;

    // prologue: xp for t=0,1 (512 tiles)
    for (int id = blockIdx.x; id < 2 * 256; id += nblk) {
        int tt = id >> 8;
        int rem = id & 255;
        int s = rem >> 5, c = rem & 31;
        gemm_tile(p.x + (size_t)tt * IND, (size_t)TT * IND,
                  p.W_in + (size_t)(c * 64) * IND, IND,
                  g_xpp[tt][s] + c * 64, HH,
                  s * 128, 128, nullptr, sA, sW);
    }
    gsync(target, nblk);

    for (int t = 0; t < TT; t++) {
        for (int l = 0; l < LL; l++) {
            // ---- pre-activation GEMM (K-split partials) ----
            if (l == 0) {
                if (t > 0) {
                    for (int id = blockIdx.x; id < SPLITS * (HH / 64); id += nblk) {
                        int s = id >> 5, n0 = (id & 31) * 64;
                        gemm_tile(g_comb[1] + HH, CK,
                                  p.fb_W + (size_t)n0 * MM, MM,
                                  g_lipart[s] + n0, HH,
                                  s * (MM / SPLITS), MM / SPLITS, nullptr, sA, sW);
                    }
                    gsync(target, nblk);
                }
            } else {
                for (int id = blockIdx.x; id < SPLITS * (HH / 64); id += nblk) {
                    int s = id >> 5, n0 = (id & 31) * 64;
                    gemm_tile(g_comb[0] + HH, CK,
                              g_Wc + (size_t)n0 * MM, MM,
                              g_lipart[s] + n0, HH,
                              s * (MM / SPLITS), MM / SPLITS, nullptr, sA, sW);
                }
                gsync(target, nblk);
            }

            // ---- layernorm over H (blocks 0..63) | xp production (blocks 64..127) ----
            if (blockIdx.x < BB) {
                int r = blockIdx.x;
                float v[8], s1 = 0.f, s2 = 0.f;
                #pragma unroll
                for (int j = 0; j < 8; j++) {
                    int h = threadIdx.x + j * 256;
                    float raw;
                    if (l == 0) {
                        raw = p.b_in[h];
                        #pragma unroll
                        for (int s = 0; s < SPLITS; s++) raw += g_xpp[t % 3][s][r * HH + h];
                        if (t > 0) {
                            float d = p.fb_b[h];
                            #pragma unroll
                            for (int s = 0; s < SPLITS; s++) d += g_lipart[s][r * HH + h];
                            raw += 0.1f * d;
                        }
                    } else {
                        float d = g_bc[h];
                        #pragma unroll
                        for (int s = 0; s < SPLITS; s++) d += g_lipart[s][r * HH + h];
                        raw = d;
                    }
                    v[j] = raw; s1 += raw; s2 += raw * raw;
                }
                float2 S = block_stats(s1, s2, red);
                float mu = S.x * (1.f / HH);
                float var = S.y * (1.f / HH) - mu * mu;
                float inv = rsqrtf(var + 1e-5f);
                #pragma unroll
                for (int j = 0; j < 8; j++) {
                    int h = threadIdx.x + j * 256;
                    g_comb[l][r * CK + h] = (v[j] - mu) * inv * p.ln_w[l * HH + h] + p.ln_b[l * HH + h];
                }
            } else {
                xp_produce(p, t, l == 0 ? 0 : 2, sA, sW);
            }
            gsync(target, nblk);

            // ---- gate GEMMs (u, r, cand), balanced K-splits ----
            {
                const float* comb = g_comb[l];
                for (int id = blockIdx.x; id < NTG; id += nblk) {
                    if (id < 8 * SU) {
                        int s = id >> 3, n0 = (id & 7) * 64;
                        int c0 = (160 * s) / SU, c1 = (160 * (s + 1)) / SU;
                        gemm_tile(comb, CK, p.upd_W + (size_t)(l * MM + n0) * CK, CK,
                                  g_upart[s] + n0, MM, c0 * 16, (c1 - c0) * 16, nullptr, sA, sW);
                    } else if (id < 16 * SU) {
                        int j = id - 8 * SU;
                        int s = j >> 3, n0 = (j & 7) * 64;
                        int c0 = (160 * s) / SU, c1 = (160 * (s + 1)) / SU;
                        gemm_tile(comb, CK, p.rst_W + (size_t)(l * MM + n0) * CK, CK,
                                  g_rpart[s] + n0, MM, c0 * 16, (c1 - c0) * 16, nullptr, sA, sW);
                    } else {
                        int j = id - 16 * SU;
                        int s = j >> 3, n0 = (j & 7) * 64;
                        int c0 = (128 * s) / SC, c1 = (128 * (s + 1)) / SC;
                        gemm_tile(comb, CK, p.cell_W + (size_t)(l * MM + n0) * HH, HH,
                                  g_cpart[s] + n0, MM, c0 * 16, (c1 - c0) * 16, nullptr, sA, sW);
                    }
                }
            }
            gsync(target, nblk);

            // ---- pointwise LTC update + mem-norm (blocks 0..63) | xp production ----
            if (blockIdx.x < BB) {
                int r = blockIdx.x;
                float hv[2], s1 = 0.f, s2 = 0.f;
                #pragma unroll
                for (int j = 0; j < 2; j++) {
                    int m = threadIdx.x + j * 256;
                    float su = p.upd_b[l * MM + m];
                    float sr = p.rst_b[l * MM + m];
                    float sc = p.cell_b[l * MM + m];
                    #pragma unroll
                    for (int s = 0; s < SU; s++) {
                        su += g_upart[s][r * MM + m];
                        sr += g_rpart[s][r * MM + m];
                    }
                    #pragma unroll
                    for (int s = 0; s < SC; s++) sc += g_cpart[s][r * MM + m];
                    float u  = 1.f / (1.f + expf(-su));
                    float rg = 1.f / (1.f + expf(-sr));
                    float c  = tanhf(sc);
                    float hold = g_comb[l][r * CK + HH + m];
                    float dec = g_dbase[l * MM + m] * u;
                    float hn = dec * (hold * rg) + (1.f - dec) * c;
                    hv[j] = hn; s1 += hn; s2 += hn * hn;
                }
                float2 S = block_stats(s1, s2, red);
                float mu = S.x * (1.f / MM);
                float var = S.y * (1.f / MM) - mu * mu;
                float inv = rsqrtf(var + 1e-5f);
                #pragma unroll
                for (int j = 0; j < 2; j++) {
                    int m = threadIdx.x + j * 256;
                    float hnorm = (hv[j] - mu) * inv * p.mn_w[l * MM + m] + p.mn_b[l * MM + m];
                    g_comb[l][r * CK + HH + m] = hnorm;
                    if (l == 1) p.out[(size_t)(r * TT + t) * MM + m] = hnorm;
                }
            } else {
                xp_produce(p, t, l == 0 ? 1 : 3, sA, sW);
            }
            gsync(target, nblk);
        }
    }

    for (int i = blockIdx.x * 256 + threadIdx.x; i < LL * BB * MM; i += nblk * 256) {
        int l = i / (BB * MM), rem = i % (BB * MM);
        p.out[(size_t)BB * TT * MM + i] = g_comb[l][(rem / MM) * CK + HH + (rem % MM)];
    }
}

extern "C" void kernel_launch(void* const* d_in, const int* in_sizes, int n_in,
                              void* d_out, int out_size) {
    (void)in_sizes; (void)n_in; (void)out_size;

    IP ip;
    ip.hidden = (const float*)d_in[1];
    ip.tau    = (const float*)d_in[10];
    ip.lc_W   = (const float*)d_in[11];
    ip.lc_b   = (const float*)d_in[12];
    ip.sk_W   = (const float*)d_in[13];
    ip.sk_b   = (const float*)d_in[14];

    SP sp;
    sp.x      = (const float*)d_in[0];
    sp.W_in   = (const float*)d_in[2];
    sp.b_in   = (const float*)d_in[3];
    sp.cell_W = (const float*)d_in[4];
    sp.cell_b = (const float*)d_in[5];
    sp.upd_W  = (const float*)d_in[6];
    sp.upd_b  = (const float*)d_in[7];
    sp.rst_W  = (const float*)d_in[8];
    sp.rst_b  = (const float*)d_in[9];
    sp.fb_W   = (const float*)d_in[15];
    sp.fb_b   = (const float*)d_in[16];
    sp.ln_w   = (const float*)d_in[17];
    sp.ln_b   = (const float*)d_in[18];
    sp.mn_w   = (const float*)d_in[19];
    sp.mn_b   = (const float*)d_in[20];
    sp.out    = (float*)d_out;

    int dev = 0;
    cudaGetDevice(&dev);
    cudaDeviceProp prop;
    cudaGetDeviceProperties(&prop, dev);
    int occ = 0;
    cudaOccupancyMaxActiveBlocksPerMultiprocessor(&occ, scan_kernel, 256, 0);
    if (occ < 1) occ = 1;
    if (occ > 2) occ = 2;
    int nblk = prop.multiProcessorCount * occ;

    init_kernel<<<256, 256>>>(ip);
    scan_kernel<<<nblk, 256>>>(sp);
}